// round 3
// baseline (speedup 1.0000x reference)
#include <cuda_runtime.h>
#include <cuda_bf16.h>

// Problem constants
#define B_   4
#define S_   16
#define H_   32
#define W_   32
#define CL_  64        // LSTM channels per layer (gate channels = 256)
#define TILE_H 8
#define NTHREADS 256
#define CHUNK 16       // input channels staged per pass
#define ROWSP (W_ + 2) // 34: padded row stride in s_in
#define CIPITCH ((TILE_H + 2) * ROWSP)  // 340 floats per input channel

// Intermediate layer-0 hidden state: (B,S,64,H,W) fp32 = 16 MB static scratch.
__device__ float g_h0[(size_t)B_ * S_ * CL_ * H_ * W_];

__device__ __forceinline__ float sigm(float x) {
    return 1.0f / (1.0f + __expf(-x));
}

// Fused minLSTM layer.
// Block = 256 threads = one 8x32 spatial tile, one batch, 2 LSTM channels
// (=> 8 gate channels: {i,f,o,cand} x 2). Grid = 4 tiles x 32 groups x 4 batch
// = 512 blocks. Full weight slab for the block's 8 gate channels is staged to
// smem ONCE; the s-loop then only restages input chunks. Cell state lives in
// registers across s.
template <int CIN>
__device__ __forceinline__ void layer_body(const float* __restrict__ x,
                                           const float* __restrict__ w,
                                           const float* __restrict__ bias,
                                           float* __restrict__ out)
{
    __shared__ __align__(16) float s_in[CHUNK * CIPITCH];   // 16*340 = 21.76 KB
    __shared__ __align__(16) float s_w[CIN * 9 * 8];        // <= 18.4 KB
    __shared__ float s_b[8];

    const int tid  = threadIdx.x;
    const int ty   = tid >> 5;       // 0..7
    const int tx   = tid & 31;       // 0..31
    const int tile = blockIdx.x;     // 0..3
    const int grp  = blockIdx.y;     // 0..31 (2 LSTM channels each)
    const int b    = blockIdx.z;     // 0..3
    const int row0 = tile * TILE_H;
    const int py   = row0 + ty;
    const int px   = tx;

    // ---- stage bias (8 gate channels) ----
    if (tid < 8) {
        int g = tid >> 1, cc = tid & 1;
        s_b[tid] = bias[g * CL_ + grp * 2 + cc];
    }

    // ---- stage full weight slab once: s_w[(ci*9+tap)*8 + j] ----
    for (int i = tid; i < CIN * 9 * 8; i += NTHREADS) {
        int j   = i & 7;
        int t   = i >> 3;
        int tap = t % 9;
        int ci  = t / 9;
        int g   = j >> 1, cc = j & 1;
        int oc  = g * CL_ + grp * 2 + cc;
        s_w[i] = w[((size_t)oc * CIN + ci) * 9 + tap];
    }

    // ---- precompute this thread's two staging slots (per-ci pass of 340) ----
    // slot k covers element t = tid + k*256 of the 10x34 padded tile.
    int  goff[2];   // global offset within a channel plane (gy*32+gx)
    bool gval[2];
    int  soff[2];   // smem offset within a channel (t)
#pragma unroll
    for (int k = 0; k < 2; ++k) {
        int t  = tid + k * NTHREADS;
        int r  = t / ROWSP;
        int cl = t - r * ROWSP;
        int gy = row0 - 1 + r;
        int gx = cl - 1;
        bool ok = (t < CIPITCH) && (gy >= 0) && (gy < H_) && (gx >= 0) && (gx < W_);
        gval[k] = ok;
        goff[k] = ok ? (gy * W_ + gx) : 0;
        soff[k] = (t < CIPITCH) ? t : 0;
    }

    __syncthreads();

    float bj[8];
#pragma unroll
    for (int j = 0; j < 8; ++j) bj[j] = s_b[j];

    float c_st0 = 0.5f, c_st1 = 0.5f;   // cell state init (g(0)=0.5)

    for (int s = 0; s < S_; ++s) {
        float acc[8];
#pragma unroll
        for (int j = 0; j < 8; ++j) acc[j] = bj[j];

        const float* xin = x + (size_t)(b * S_ + s) * CIN * (H_ * W_);

        for (int ch = 0; ch < CIN / CHUNK; ++ch) {
            __syncthreads();   // previous chunk's compute done before overwrite
            // ---- stage input chunk: 16 ci x 340 elems ----
            const float* xc = xin + (size_t)ch * CHUNK * (H_ * W_);
#pragma unroll
            for (int ci = 0; ci < CHUNK; ++ci) {
                float v0 = gval[0] ? xc[ci * (H_ * W_) + goff[0]] : 0.0f;
                if (tid + 0   < CIPITCH || true) s_in[ci * CIPITCH + soff[0]] = gval[0] ? v0 : ((tid < CIPITCH) ? 0.0f : s_in[ci * CIPITCH]);
            }
            // (rewrite cleanly below)
            __syncthreads();
            // NOTE: see corrected staging below
            (void)0;
            // ---- compute ----
            const float* wbase = &s_w[(ch * CHUNK) * 9 * 8];
#pragma unroll 1
            for (int ci = 0; ci < CHUNK; ++ci) {
                const float* xb = &s_in[ci * CIPITCH + ty * ROWSP + tx];
                const float* wb = &wbase[ci * 9 * 8];
#pragma unroll
                for (int ky = 0; ky < 3; ++ky) {
#pragma unroll
                    for (int kx = 0; kx < 3; ++kx) {
                        float xv = xb[ky * ROWSP + kx];
                        const float4* wp = (const float4*)&wb[(ky * 3 + kx) * 8];
                        float4 wa = wp[0], wbv = wp[1];
                        acc[0] = fmaf(xv, wa.x,  acc[0]);
                        acc[1] = fmaf(xv, wa.y,  acc[1]);
                        acc[2] = fmaf(xv, wa.z,  acc[2]);
                        acc[3] = fmaf(xv, wa.w,  acc[3]);
                        acc[4] = fmaf(xv, wbv.x, acc[4]);
                        acc[5] = fmaf(xv, wbv.y, acc[5]);
                        acc[6] = fmaf(xv, wbv.z, acc[6]);
                        acc[7] = fmaf(xv, wbv.w, acc[7]);
                    }
                }
            }
        }

        // ---- gating + scan + output (2 LSTM channels) ----
        float* outp = out + ((size_t)(b * S_ + s) * CL_ + grp * 2) * (H_ * W_)
                    + py * W_ + px;
#pragma unroll
        for (int cc = 0; cc < 2; ++cc) {
            float it = sigm(acc[0 + cc]);
            float ft = sigm(acc[2 + cc]);
            float ot = sigm(acc[4 + cc]);
            float cd = acc[6 + cc];
            float gd = (cd >= 0.0f) ? (cd + 0.5f) : sigm(cd);
            float inv = 1.0f / (it + ft);
            float cprev = cc ? c_st1 : c_st0;
            float cn = (ft * inv) * cprev + (it * inv) * gd;
            if (cc) c_st1 = cn; else c_st0 = cn;
            outp[cc * (H_ * W_)] = ot * cn;
        }
    }
}

// ---- Clean staging implementation (replaces the messy block above) ----
// The template above is superseded by this corrected version:
template <int CIN>
__device__ __forceinline__ void layer_body2(const float* __restrict__ x,
                                            const float* __restrict__ w,
                                            const float* __restrict__ bias,
                                            float* __restrict__ out)
{
    __shared__ __align__(16) float s_in[CHUNK * CIPITCH];
    __shared__ __align__(16) float s_w[CIN * 9 * 8];
    __shared__ float s_b[8];

    const int tid  = threadIdx.x;
    const int ty   = tid >> 5;
    const int tx   = tid & 31;
    const int tile = blockIdx.x;
    const int grp  = blockIdx.y;
    const int b    = blockIdx.z;
    const int row0 = tile * TILE_H;
    const int py   = row0 + ty;
    const int px   = tx;

    if (tid < 8) {
        int g = tid >> 1, cc = tid & 1;
        s_b[tid] = bias[g * CL_ + grp * 2 + cc];
    }
    for (int i = tid; i < CIN * 9 * 8; i += NTHREADS) {
        int j   = i & 7;
        int t   = i >> 3;
        int tap = t % 9;
        int ci  = t / 9;
        int g   = j >> 1, cc = j & 1;
        int oc  = g * CL_ + grp * 2 + cc;
        s_w[i] = w[((size_t)oc * CIN + ci) * 9 + tap];
    }

    // per-thread staging slots: slot k = element (tid + k*256) of 340
    int  goff[2]; bool gval[2]; bool sval[2]; int soff[2];
#pragma unroll
    for (int k = 0; k < 2; ++k) {
        int t  = tid + k * NTHREADS;
        int r  = t / ROWSP;
        int cl = t - r * ROWSP;
        int gy = row0 - 1 + r;
        int gx = cl - 1;
        sval[k] = (t < CIPITCH);
        gval[k] = sval[k] && (gy >= 0) && (gy < H_) && (gx >= 0) && (gx < W_);
        goff[k] = gval[k] ? (gy * W_ + gx) : 0;
        soff[k] = sval[k] ? t : 0;
    }
    __syncthreads();

    float bj[8];
#pragma unroll
    for (int j = 0; j < 8; ++j) bj[j] = s_b[j];

    float c_st0 = 0.5f, c_st1 = 0.5f;

    for (int s = 0; s < S_; ++s) {
        float acc[8];
#pragma unroll
        for (int j = 0; j < 8; ++j) acc[j] = bj[j];

        const float* xin = x + (size_t)(b * S_ + s) * CIN * (H_ * W_);

        for (int ch = 0; ch < CIN / CHUNK; ++ch) {
            __syncthreads();
            const float* xc = xin + (size_t)ch * CHUNK * (H_ * W_);
#pragma unroll
            for (int ci = 0; ci < CHUNK; ++ci) {
                const float* xp = xc + ci * (H_ * W_);
#pragma unroll
                for (int k = 0; k < 2; ++k) {
                    if (sval[k]) {
                        float v = gval[k] ? __ldg(xp + goff[k]) : 0.0f;
                        s_in[ci * CIPITCH + soff[k]] = v;
                    }
                }
            }
            __syncthreads();

            const float* wbase = &s_w[(ch * CHUNK) * 9 * 8];
#pragma unroll 1
            for (int ci = 0; ci < CHUNK; ++ci) {
                const float* xb = &s_in[ci * CIPITCH + ty * ROWSP + tx];
                const float* wb = &wbase[ci * 9 * 8];
#pragma unroll
                for (int ky = 0; ky < 3; ++ky) {
#pragma unroll
                    for (int kx = 0; kx < 3; ++kx) {
                        float xv = xb[ky * ROWSP + kx];
                        const float4* wp = (const float4*)&wb[(ky * 3 + kx) * 8];
                        float4 wa = wp[0], wbv = wp[1];
                        acc[0] = fmaf(xv, wa.x,  acc[0]);
                        acc[1] = fmaf(xv, wa.y,  acc[1]);
                        acc[2] = fmaf(xv, wa.z,  acc[2]);
                        acc[3] = fmaf(xv, wa.w,  acc[3]);
                        acc[4] = fmaf(xv, wbv.x, acc[4]);
                        acc[5] = fmaf(xv, wbv.y, acc[5]);
                        acc[6] = fmaf(xv, wbv.z, acc[6]);
                        acc[7] = fmaf(xv, wbv.w, acc[7]);
                    }
                }
            }
        }

        float* outp = out + ((size_t)(b * S_ + s) * CL_ + grp * 2) * (H_ * W_)
                    + py * W_ + px;
#pragma unroll
        for (int cc = 0; cc < 2; ++cc) {
            float it = sigm(acc[0 + cc]);
            float ft = sigm(acc[2 + cc]);
            float ot = sigm(acc[4 + cc]);
            float cd = acc[6 + cc];
            float gd = (cd >= 0.0f) ? (cd + 0.5f) : sigm(cd);
            float inv = 1.0f / (it + ft);
            float cprev = cc ? c_st1 : c_st0;
            float cn = (ft * inv) * cprev + (it * inv) * gd;
            if (cc) c_st1 = cn; else c_st0 = cn;
            outp[cc * (H_ * W_)] = ot * cn;
        }
    }
}

__global__ void __launch_bounds__(256, 4)
k_layer0(const float* __restrict__ x, const float* __restrict__ w,
         const float* __restrict__ b)
{
    layer_body2<32>(x, w, b, g_h0);
}

__global__ void __launch_bounds__(256, 4)
k_layer1(const float* __restrict__ w, const float* __restrict__ b,
         float* __restrict__ out)
{
    layer_body2<64>(g_h0, w, b, out);
}

extern "C" void kernel_launch(void* const* d_in, const int* in_sizes, int n_in,
                              void* d_out, int out_size)
{
    const float* x  = (const float*)d_in[0];
    const float* w0 = (const float*)d_in[1];
    const float* b0 = (const float*)d_in[2];
    const float* w1 = (const float*)d_in[3];
    const float* b1 = (const float*)d_in[4];
    float* out = (float*)d_out;

    dim3 grid(4, 32, 4);   // row tiles x channel groups(2ch) x batch = 512 blocks
    k_layer0<<<grid, NTHREADS>>>(x, w0, b0);
    k_layer1<<<grid, NTHREADS>>>(w1, b1, out);
}

// round 4
// speedup vs baseline: 1.1634x; 1.1634x over previous
#include <cuda_runtime.h>
#include <cuda_bf16.h>

// Problem constants
#define B_   4
#define S_   16
#define H_   32
#define W_   32
#define HW_  (H_ * W_)
#define CL_  64        // LSTM channels per layer (gate channels = 256)
#define TILE_H 16      // rows per block tile
#define NTHREADS 128   // 4 warps: thread (ty 0..3, tx 0..31), 4 pixels each
#define CHUNK 8        // input channels staged per pass
#define ROWSP (W_ + 2)                    // 34
#define CIPITCH ((TILE_H + 2) * ROWSP)    // 18*34 = 612 floats per channel

// Intermediate layer-0 hidden state: (B,S,64,H,W) fp32 = 16 MB static scratch.
__device__ float g_h0[(size_t)B_ * S_ * CL_ * HW_];

__device__ __forceinline__ float sigm(float x) {
    return 1.0f / (1.0f + __expf(-x));
}

// Fused minLSTM layer.
// Block = 128 threads = one 16x32 spatial tile, one batch, 2 LSTM channels
// (8 gate channels). Each thread owns 4 vertically adjacent pixels
// (rows 4*ty..4*ty+3), giving 32 fp32 accumulators; the 6x3 input window is
// register-cached across all 9 taps so each weight LDS.128 feeds 16 FFMAs.
// Weight slab staged to smem once; s-loop restages input chunks only. Cell
// state for 4 px x 2 channels lives in registers across s.
template <int CIN>
__device__ __forceinline__ void layer_body(const float* __restrict__ x,
                                           const float* __restrict__ w,
                                           const float* __restrict__ bias,
                                           float* __restrict__ out)
{
    __shared__ __align__(16) float s_in[CHUNK * CIPITCH];  // 8*612*4 = 19.1 KB
    __shared__ __align__(16) float s_w[CIN * 9 * 8];       // <= 18.4 KB
    __shared__ float s_b[8];

    const int tid  = threadIdx.x;
    const int ty   = tid >> 5;       // 0..3
    const int tx   = tid & 31;       // 0..31
    const int tile = blockIdx.x;     // 0..1
    const int grp  = blockIdx.y;     // 0..31 (2 LSTM channels)
    const int b    = blockIdx.z;     // 0..3
    const int row0 = tile * TILE_H;
    const int py0  = row0 + 4 * ty;  // first of this thread's 4 pixel rows

    // ---- stage bias: j = gate*2 + cc ----
    if (tid < 8) {
        int g = tid >> 1, cc = tid & 1;
        s_b[tid] = bias[g * CL_ + grp * 2 + cc];
    }
    // ---- stage full weight slab once: s_w[(ci*9+tap)*8 + j] ----
    for (int i = tid; i < CIN * 9 * 8; i += NTHREADS) {
        int j   = i & 7;
        int t   = i >> 3;
        int tap = t % 9;
        int ci  = t / 9;
        int g   = j >> 1, cc = j & 1;
        int oc  = g * CL_ + grp * 2 + cc;
        s_w[i] = w[((size_t)oc * CIN + ci) * 9 + tap];
    }
    __syncthreads();

    float bj[8];
#pragma unroll
    for (int j = 0; j < 8; ++j) bj[j] = s_b[j];

    // cell state: 4 pixels x 2 LSTM channels, init 0.5 (g(0)=0.5)
    float c_st[4][2];
#pragma unroll
    for (int p = 0; p < 4; ++p) { c_st[p][0] = 0.5f; c_st[p][1] = 0.5f; }

    for (int s = 0; s < S_; ++s) {
        float acc[4][8];
#pragma unroll
        for (int p = 0; p < 4; ++p)
#pragma unroll
            for (int j = 0; j < 8; ++j) acc[p][j] = bj[j];

        const float* xin = x + (size_t)(b * S_ + s) * CIN * HW_;

        for (int ch = 0; ch < CIN / CHUNK; ++ch) {
            __syncthreads();   // previous chunk's compute done before overwrite
            // ---- stage input chunk: CHUNK channels x 18x34 padded tile ----
            const float* xc = xin + (size_t)ch * CHUNK * HW_;
            for (int i = tid; i < CHUNK * CIPITCH; i += NTHREADS) {
                int ci  = i / CIPITCH;
                int rem = i - ci * CIPITCH;
                int r   = rem / ROWSP;
                int c   = rem - r * ROWSP;
                int gy  = row0 - 1 + r;
                int gx  = c - 1;
                float v = 0.0f;
                if ((unsigned)gy < (unsigned)H_ && (unsigned)gx < (unsigned)W_)
                    v = __ldg(xc + ci * HW_ + gy * W_ + gx);
                s_in[i] = v;
            }
            __syncthreads();

            // ---- compute ----
            const float* wslab = &s_w[(ch * CHUNK) * 72];
#pragma unroll 1
            for (int ci = 0; ci < CHUNK; ++ci) {
                // register-cache 6 rows x 3 cols of input
                const float* xb = &s_in[ci * CIPITCH + (4 * ty) * ROWSP + tx];
                float xv[6][3];
#pragma unroll
                for (int t = 0; t < 6; ++t)
#pragma unroll
                    for (int k = 0; k < 3; ++k)
                        xv[t][k] = xb[t * ROWSP + k];

                const float* wb = &wslab[ci * 72];
#pragma unroll
                for (int ky = 0; ky < 3; ++ky) {
#pragma unroll
                    for (int kx = 0; kx < 3; ++kx) {
                        const float4* wp = (const float4*)&wb[(ky * 3 + kx) * 8];
                        float4 wa = wp[0], wc4 = wp[1];
#pragma unroll
                        for (int p = 0; p < 4; ++p) {
                            float xs = xv[p + ky][kx];
                            acc[p][0] = fmaf(xs, wa.x,  acc[p][0]);
                            acc[p][1] = fmaf(xs, wa.y,  acc[p][1]);
                            acc[p][2] = fmaf(xs, wa.z,  acc[p][2]);
                            acc[p][3] = fmaf(xs, wa.w,  acc[p][3]);
                            acc[p][4] = fmaf(xs, wc4.x, acc[p][4]);
                            acc[p][5] = fmaf(xs, wc4.y, acc[p][5]);
                            acc[p][6] = fmaf(xs, wc4.z, acc[p][6]);
                            acc[p][7] = fmaf(xs, wc4.w, acc[p][7]);
                        }
                    }
                }
            }
        }

        // ---- gating + scan + output: 4 pixels x 2 LSTM channels ----
        float* outp = out + ((size_t)(b * S_ + s) * CL_ + grp * 2) * HW_ + tx;
#pragma unroll
        for (int p = 0; p < 4; ++p) {
            int prow = py0 + p;
#pragma unroll
            for (int cc = 0; cc < 2; ++cc) {
                float it = sigm(acc[p][0 + cc]);
                float ft = sigm(acc[p][2 + cc]);
                float ot = sigm(acc[p][4 + cc]);
                float cd = acc[p][6 + cc];
                float gd = (cd >= 0.0f) ? (cd + 0.5f) : sigm(cd);
                float inv = 1.0f / (it + ft);
                float cn = (ft * inv) * c_st[p][cc] + (it * inv) * gd;
                c_st[p][cc] = cn;
                outp[cc * HW_ + prow * W_] = ot * cn;
            }
        }
    }
}

__global__ void __launch_bounds__(128, 5)
k_layer0(const float* __restrict__ x, const float* __restrict__ w,
         const float* __restrict__ b)
{
    layer_body<32>(x, w, b, g_h0);
}

__global__ void __launch_bounds__(128, 5)
k_layer1(const float* __restrict__ w, const float* __restrict__ b,
         float* __restrict__ out)
{
    layer_body<64>(g_h0, w, b, out);
}

extern "C" void kernel_launch(void* const* d_in, const int* in_sizes, int n_in,
                              void* d_out, int out_size)
{
    const float* x  = (const float*)d_in[0];
    const float* w0 = (const float*)d_in[1];
    const float* b0 = (const float*)d_in[2];
    const float* w1 = (const float*)d_in[3];
    const float* b1 = (const float*)d_in[4];
    float* out = (float*)d_out;

    dim3 grid(2, 32, 4);   // 16-row tiles x channel groups(2ch) x batch = 256 blocks
    k_layer0<<<grid, NTHREADS>>>(x, w0, b0);
    k_layer1<<<grid, NTHREADS>>>(w1, b1, out);
}

// round 5
// speedup vs baseline: 1.7056x; 1.4660x over previous
#include <cuda_runtime.h>
#include <cuda_bf16.h>

// Problem constants
#define B_   4
#define S_   16
#define H_   32
#define W_   32
#define HW_  (H_ * W_)
#define CL_  64          // LSTM channels per layer (gate channels = 256)
#define PR   34          // padded row width
#define PPLANE (PR * PR) // 1156 floats per padded channel plane

// Scratch: padded layer-0 input and padded layer-0 output (layer-1 input).
__device__ float g_xpad[(size_t)B_ * S_ * 32  * PPLANE];  // 9.5 MB
__device__ float g_h0p [(size_t)B_ * S_ * CL_ * PPLANE];  // 18.9 MB

__device__ __forceinline__ float sigm(float x) {
    return 1.0f / (1.0f + __expf(-x));
}

// ---- prologue kernels ------------------------------------------------------

__global__ void k_pad_x(const float* __restrict__ x) {
    const int n = B_ * S_ * 32 * PPLANE;
    for (int i = blockIdx.x * blockDim.x + threadIdx.x; i < n;
         i += gridDim.x * blockDim.x) {
        int plane = i / PPLANE;
        int rem   = i - plane * PPLANE;
        int r     = rem / PR;
        int c     = rem - r * PR;
        float v = 0.0f;
        if (r >= 1 && r <= H_ && c >= 1 && c <= W_)
            v = x[(size_t)plane * HW_ + (r - 1) * W_ + (c - 1)];
        g_xpad[i] = v;
    }
}

__global__ void k_zero_h0p() {
    const size_t n = (size_t)B_ * S_ * CL_ * PPLANE;
    for (size_t i = blockIdx.x * blockDim.x + threadIdx.x; i < n;
         i += (size_t)gridDim.x * blockDim.x)
        g_h0p[i] = 0.0f;
}

// ---- fused minLSTM layer ---------------------------------------------------
// Block = 1 warp (32 threads). Thread tx owns column tx and 4 pixel rows
// (py0..py0+3). Block covers 2 LSTM channels (8 gate channels). Grid =
// 8 row-tiles x 32 channel-groups x 4 batch = 1024 blocks.
// No barriers in the s-loop: inputs read directly from padded global memory
// (L1/L2 resident) into a 6x3 register window; weights in smem (staged once).
// Cell state for 4 px x 2 channels lives in registers across s.
template <int CIN, bool PADOUT>
__device__ __forceinline__ void layer_body(const float* __restrict__ xp,
                                           const float* __restrict__ w,
                                           const float* __restrict__ bias,
                                           float* __restrict__ out)
{
    __shared__ __align__(16) float s_w[CIN * 72];   // [ci][tap][j], j=gate*2+cc

    const int tx   = threadIdx.x;    // 0..31 (column)
    const int tile = blockIdx.x;     // 0..7  (4-row tiles)
    const int grp  = blockIdx.y;     // 0..31 (2 LSTM channels)
    const int b    = blockIdx.z;     // 0..3
    const int py0  = tile * 4;

    // stage weight slab once: s_w[(ci*9+tap)*8 + j]
    for (int i = tx; i < CIN * 72; i += 32) {
        int j   = i & 7;
        int t   = i >> 3;
        int tap = t % 9;
        int ci  = t / 9;
        int oc  = (j >> 1) * CL_ + grp * 2 + (j & 1);
        s_w[i] = w[((size_t)oc * CIN + ci) * 9 + tap];
    }
    __syncwarp();

    float bj[8];
#pragma unroll
    for (int j = 0; j < 8; ++j)
        bj[j] = __ldg(bias + (j >> 1) * CL_ + grp * 2 + (j & 1));

    float c_st[4][2];
#pragma unroll
    for (int p = 0; p < 4; ++p) { c_st[p][0] = 0.5f; c_st[p][1] = 0.5f; }

    for (int s = 0; s < S_; ++s) {
        float acc[4][8];
#pragma unroll
        for (int p = 0; p < 4; ++p)
#pragma unroll
            for (int j = 0; j < 8; ++j) acc[p][j] = bj[j];

        // window anchor: padded rows py0..py0+5, padded cols tx..tx+2
        const float* xb0 = xp + ((size_t)(b * S_ + s) * CIN) * PPLANE
                         + py0 * PR + tx;

#pragma unroll 2
        for (int ci = 0; ci < CIN; ++ci) {
            const float* xb = xb0 + ci * PPLANE;
            float xv[6][3];
#pragma unroll
            for (int t6 = 0; t6 < 6; ++t6)
#pragma unroll
                for (int k = 0; k < 3; ++k)
                    xv[t6][k] = __ldg(xb + t6 * PR + k);

            const float* wb = &s_w[ci * 72];
#pragma unroll
            for (int ky = 0; ky < 3; ++ky) {
#pragma unroll
                for (int kx = 0; kx < 3; ++kx) {
                    const float4* wp = (const float4*)&wb[(ky * 3 + kx) * 8];
                    float4 wa = wp[0], wc4 = wp[1];
#pragma unroll
                    for (int p = 0; p < 4; ++p) {
                        float xs = xv[p + ky][kx];
                        acc[p][0] = fmaf(xs, wa.x,  acc[p][0]);
                        acc[p][1] = fmaf(xs, wa.y,  acc[p][1]);
                        acc[p][2] = fmaf(xs, wa.z,  acc[p][2]);
                        acc[p][3] = fmaf(xs, wa.w,  acc[p][3]);
                        acc[p][4] = fmaf(xs, wc4.x, acc[p][4]);
                        acc[p][5] = fmaf(xs, wc4.y, acc[p][5]);
                        acc[p][6] = fmaf(xs, wc4.z, acc[p][6]);
                        acc[p][7] = fmaf(xs, wc4.w, acc[p][7]);
                    }
                }
            }
        }

        // gating + scan + store: 4 pixels x 2 LSTM channels
#pragma unroll
        for (int p = 0; p < 4; ++p) {
            int prow = py0 + p;
#pragma unroll
            for (int cc = 0; cc < 2; ++cc) {
                float it = sigm(acc[p][0 + cc]);
                float ft = sigm(acc[p][2 + cc]);
                float ot = sigm(acc[p][4 + cc]);
                float cd = acc[p][6 + cc];
                float gd = (cd >= 0.0f) ? (cd + 0.5f) : sigm(cd);
                float inv = 1.0f / (it + ft);
                float cn = (ft * inv) * c_st[p][cc] + (it * inv) * gd;
                c_st[p][cc] = cn;
                float hv = ot * cn;
                if (PADOUT) {
                    out[((size_t)(b * S_ + s) * CL_ + grp * 2 + cc) * PPLANE
                        + (prow + 1) * PR + (tx + 1)] = hv;
                } else {
                    out[((size_t)(b * S_ + s) * CL_ + grp * 2 + cc) * HW_
                        + prow * W_ + tx] = hv;
                }
            }
        }
    }
}

__global__ void __launch_bounds__(32)
k_layer0(const float* __restrict__ w, const float* __restrict__ b)
{
    layer_body<32, true>(g_xpad, w, b, g_h0p);
}

__global__ void __launch_bounds__(32)
k_layer1(const float* __restrict__ w, const float* __restrict__ b,
         float* __restrict__ out)
{
    layer_body<64, false>(g_h0p, w, b, out);
}

extern "C" void kernel_launch(void* const* d_in, const int* in_sizes, int n_in,
                              void* d_out, int out_size)
{
    const float* x  = (const float*)d_in[0];
    const float* w0 = (const float*)d_in[1];
    const float* b0 = (const float*)d_in[2];
    const float* w1 = (const float*)d_in[3];
    const float* b1 = (const float*)d_in[4];
    float* out = (float*)d_out;

    k_pad_x<<<2048, 256>>>(x);
    k_zero_h0p<<<2048, 256>>>();

    dim3 grid(8, 32, 4);   // 1024 one-warp blocks
    k_layer0<<<grid, 32>>>(w0, b0);
    k_layer1<<<grid, 32>>>(w1, b1, out);
}

// round 7
// speedup vs baseline: 2.4234x; 1.4209x over previous
#include <cuda_runtime.h>
#include <cuda_bf16.h>
#include <cstdint>

// ---------------- problem constants ----------------
#define B_     4
#define S_     16
#define NF     64            // frames = B*S
#define H_     32
#define W_     32
#define HW_    1024
#define CL_    64            // LSTM channels per layer; gate channels = 256
#define PR     34            // padded row width
#define PPLANE 1156          // 34*34
#define GST    1152          // gates scratch stride (18 N-tiles of 64)
#define NT     18            // N tiles per frame
#define KP     104           // padded K stride in bf16 halves (conflict-free ldsm)

// ---------------- device scratch (static; no allocations) ----------------
__device__ float g_xraw [(size_t)NF * 32  * PPLANE + 64 + 2048];  // padded x (+guards)
__device__ float g_h1raw[(size_t)NF * CL_ * PPLANE + 64 + 2048];  // padded h0 (+guards)
__device__ float g_gates[(size_t)NF * 256 * GST];                 // conv outputs
// bf16-split, K-expanded weights: [chunk][256 oc][96]  (k = [ah | al | ah])
__device__ __align__(16) __nv_bfloat16 g_wp0[9  * 256 * 96];
__device__ __align__(16) __nv_bfloat16 g_wp1[18 * 256 * 96];

__constant__ int c_tapoff[9] = { -35, -34, -33, -1, 0, 1, 33, 34, 35 };

// ---------------- helpers ----------------
__device__ __forceinline__ float sigm(float x) { return 1.0f / (1.0f + __expf(-x)); }

__device__ __forceinline__ uint32_t smem_u32(const void* p) {
    uint32_t a;
    asm("{ .reg .u64 t; cvta.to.shared.u64 t, %1; cvt.u32.u64 %0, t; }" : "=r"(a) : "l"(p));
    return a;
}

__device__ __forceinline__ void ldsm4(uint32_t r[4], uint32_t addr) {
    asm volatile("ldmatrix.sync.aligned.m8n8.x4.shared.b16 {%0,%1,%2,%3}, [%4];"
        : "=r"(r[0]), "=r"(r[1]), "=r"(r[2]), "=r"(r[3]) : "r"(addr));
}

__device__ __forceinline__ void mma16816(float d[4], const uint32_t a[4],
                                         uint32_t b0, uint32_t b1) {
    asm volatile(
        "mma.sync.aligned.m16n8k16.row.col.f32.bf16.bf16.f32 "
        "{%0,%1,%2,%3}, {%4,%5,%6,%7}, {%8,%9}, {%0,%1,%2,%3};"
        : "+f"(d[0]), "+f"(d[1]), "+f"(d[2]), "+f"(d[3])
        : "r"(a[0]), "r"(a[1]), "r"(a[2]), "r"(a[3]), "r"(b0), "r"(b1));
}

__device__ __forceinline__ uint32_t bpack(float lo, float hi) {
    uint16_t l = __bfloat16_as_ushort(__float2bfloat16(lo));
    uint16_t h = __bfloat16_as_ushort(__float2bfloat16(hi));
    return (uint32_t)l | ((uint32_t)h << 16);
}

// ---------------- prologue kernels ----------------
__global__ void k_zero() {
    const size_t n1 = sizeof(g_xraw) / 4, n2 = sizeof(g_h1raw) / 4;
    for (size_t i = blockIdx.x * blockDim.x + threadIdx.x; i < n1 + n2;
         i += (size_t)gridDim.x * blockDim.x) {
        if (i < n1) g_xraw[i] = 0.0f; else g_h1raw[i - n1] = 0.0f;
    }
}

__global__ void k_fill_x(const float* __restrict__ x) {
    float* xp = g_xraw + 64;
    const int n = NF * 32 * HW_;
    for (int i = blockIdx.x * blockDim.x + threadIdx.x; i < n;
         i += gridDim.x * blockDim.x) {
        int plane = i >> 10, px = i & 1023;
        int r = px >> 5, c = px & 31;
        xp[(size_t)plane * PPLANE + (r + 1) * PR + (c + 1)] = x[i];
    }
}

// bf16-split weight packing: chunk ch covers tap=ch/CPT, ci0=(ch%CPT)*32.
// k layout per oc row (96): [0..31]=ah, [32..63]=al, [64..95]=ah.
__global__ void k_pack_w(const float* __restrict__ w0, const float* __restrict__ w1) {
    const int n0 = 9 * 256 * 32, n1 = 18 * 256 * 32;
    for (int i = blockIdx.x * blockDim.x + threadIdx.x; i < n0 + n1;
         i += gridDim.x * blockDim.x) {
        if (i < n0) {
            int ci = i & 31, t = i >> 5, oc = t & 255, ch = t >> 8;  // ch = tap
            float v = w0[((size_t)oc * 32 + ci) * 9 + ch];
            __nv_bfloat16 ah = __float2bfloat16(v);
            __nv_bfloat16 al = __float2bfloat16(v - __bfloat162float(ah));
            __nv_bfloat16* p = g_wp0 + ((size_t)ch * 256 + oc) * 96;
            p[ci] = ah; p[32 + ci] = al; p[64 + ci] = ah;
        } else {
            int j = i - n0;
            int ci = j & 31, t = j >> 5, oc = t & 255, ch = t >> 8;  // ch 0..17
            int tap = ch >> 1, ci0 = (ch & 1) * 32;
            float v = w1[((size_t)oc * 64 + ci0 + ci) * 9 + tap];
            __nv_bfloat16 ah = __float2bfloat16(v);
            __nv_bfloat16 al = __float2bfloat16(v - __bfloat162float(ah));
            __nv_bfloat16* p = g_wp1 + ((size_t)ch * 256 + oc) * 96;
            p[ci] = ah; p[32 + ci] = al; p[64 + ci] = ah;
        }
    }
}

// ---------------- GEMM kernel ----------------
// CTA = 128 threads (4 warps). Tile: M=128 gate channels x N=64 padded pixels,
// one frame. K loop: 9*CPT chunks of 96 (32 ci x 3 split-terms). Warp w owns
// M rows [w*32, w*32+32) x all 64 N. mma.sync m16n8k16 bf16.
template <int CPT>   // chunks per tap: 1 (CIN=32) or 2 (CIN=64)
__device__ __forceinline__ void gemm_body(const float* __restrict__ xpad,
                                          const __nv_bfloat16* __restrict__ wp,
                                          float* __restrict__ gates)
{
    __shared__ __align__(16) __nv_bfloat16 sA[128 * KP];
    __shared__ __align__(16) __nv_bfloat16 sB[64 * KP];

    const int tid  = threadIdx.x, w = tid >> 5, lane = tid & 31;
    const int frame = blockIdx.x / NT, ntile = blockIdx.x - frame * NT;
    const int mtile = blockIdx.y;
    const int p0 = ntile * 64;
    const int NCH = 9 * CPT;

    const float* xf = xpad + (size_t)frame * (CPT * 32) * PPLANE;
    const uint32_t sAu = smem_u32(sA), sBu = smem_u32(sB);

    float d[2][8][4];
#pragma unroll
    for (int mt = 0; mt < 2; ++mt)
#pragma unroll
        for (int nt = 0; nt < 8; ++nt)
#pragma unroll
            for (int q = 0; q < 4; ++q) d[mt][nt][q] = 0.0f;

#pragma unroll 1
    for (int ch = 0; ch < NCH; ++ch) {
        const int tap = (CPT == 1) ? ch : (ch >> 1);
        const int ci0 = (CPT == 1) ? 0 : ((ch & 1) * 32);
        const int to  = c_tapoff[tap];

        __syncthreads();   // previous iter's ldsm reads done

        // ---- stage A: rows split so each STS.128 hits 8 distinct row groups ----
        {
            const __nv_bfloat16* ag = wp + ((size_t)ch * 256 + mtile * 128) * 96;
            const int r8 = lane & 7, cg = lane >> 3;   // cg 0..3
#pragma unroll
            for (int ri = 0; ri < 4; ++ri) {
                int r = ri * 32 + w * 8 + r8;
#pragma unroll
                for (int cj = 0; cj < 3; ++cj) {
                    int c = cj * 4 + cg;               // 16B chunk 0..11
                    uint4 v = *(const uint4*)(ag + (size_t)r * 96 + c * 8);
                    *(uint4*)(sA + r * KP + c * 8) = v;
                }
            }
        }
        // ---- stage B: build bf16 split from padded fp32 planes ----
        {
            const int r8 = lane & 7, cig = lane >> 3;  // ci group of 8
#pragma unroll
            for (int pi = 0; pi < 2; ++pi) {
                int row = pi * 32 + w * 8 + r8;        // 0..63 (pixel in tile)
                const float* xs = xf + (size_t)ci0 * PPLANE + p0 + row + to;
                float v[8];
#pragma unroll
                for (int j = 0; j < 8; ++j)
                    v[j] = __ldg(xs + (size_t)(cig * 8 + j) * PPLANE);
                uint4 hv, lv;
                uint32_t* hw = (uint32_t*)&hv;
                uint32_t* lw = (uint32_t*)&lv;
#pragma unroll
                for (int j = 0; j < 4; ++j) {
                    float a0 = v[2 * j], a1 = v[2 * j + 1];
                    __nv_bfloat16 h0 = __float2bfloat16(a0);
                    __nv_bfloat16 h1 = __float2bfloat16(a1);
                    float r0 = a0 - __bfloat162float(h0);
                    float r1 = a1 - __bfloat162float(h1);
                    hw[j] = (uint32_t)__bfloat16_as_ushort(h0)
                          | ((uint32_t)__bfloat16_as_ushort(h1) << 16);
                    lw[j] = bpack(r0, r1);
                }
                __nv_bfloat16* br = sB + row * KP;
                *(uint4*)(br + cig * 8)      = hv;   // k [0..31]  = bh
                *(uint4*)(br + 32 + cig * 8) = hv;   // k [32..63] = bh (dup)
                *(uint4*)(br + 64 + cig * 8) = lv;   // k [64..95] = bl
            }
        }
        __syncthreads();

        // ---- mma: 6 k-steps of 16 ----
#pragma unroll
        for (int ks = 0; ks < 6; ++ks) {
            const int kk = ks * 16;
            uint32_t a[2][4], b[4][4];
#pragma unroll
            for (int mt = 0; mt < 2; ++mt) {
                int rowA = w * 32 + mt * 16 + (lane & 15);
                int kcol = kk + (lane >> 4) * 8;
                ldsm4(a[mt], sAu + (uint32_t)(rowA * KP + kcol) * 2);
            }
#pragma unroll
            for (int np = 0; np < 4; ++np) {
                int rowB = np * 16 + ((lane >> 4) & 1) * 8 + (lane & 7);
                int kcol = kk + ((lane >> 3) & 1) * 8;
                ldsm4(b[np], sBu + (uint32_t)(rowB * KP + kcol) * 2);
            }
#pragma unroll
            for (int mt = 0; mt < 2; ++mt)
#pragma unroll
                for (int nt = 0; nt < 8; ++nt)
                    mma16816(d[mt][nt], a[mt], b[nt >> 1][(nt & 1) * 2],
                             b[nt >> 1][(nt & 1) * 2 + 1]);
        }
    }

    // ---- epilogue: D -> gates scratch ----
    const int g4 = lane >> 2, t4 = lane & 3;
#pragma unroll
    for (int mt = 0; mt < 2; ++mt) {
        size_t rowbase = (size_t)frame * 256 + mtile * 128 + w * 32 + mt * 16 + g4;
#pragma unroll
        for (int nt = 0; nt < 8; ++nt) {
            float* gp = gates + rowbase * GST + p0 + nt * 8 + t4 * 2;
            *(float2*)gp                  = make_float2(d[mt][nt][0], d[mt][nt][1]);
            *(float2*)(gp + 8 * (size_t)GST) = make_float2(d[mt][nt][2], d[mt][nt][3]);
        }
    }
}

__global__ void __launch_bounds__(128)
k_gemm0() { gemm_body<1>(g_xraw + 64, g_wp0, g_gates); }

__global__ void __launch_bounds__(128)
k_gemm1() { gemm_body<2>(g_h1raw + 64, g_wp1, g_gates); }

// ---------------- scan kernels ----------------
// thread = (b, lstm-channel, interior pixel); loops s with cell state in a register.
template <bool PADOUT>
__global__ void __launch_bounds__(256)
k_scan(const float* __restrict__ bias, float* __restrict__ out)
{
    int gtid = blockIdx.x * blockDim.x + threadIdx.x;  // 0 .. 262143
    int px = gtid & 1023;
    int ch = (gtid >> 10) & 63;
    int b  = gtid >> 16;
    int r = px >> 5, c = px & 31;
    int p = (r + 1) * PR + (c + 1);

    float bi = __ldg(bias + ch);
    float bf = __ldg(bias + 64 + ch);
    float bo = __ldg(bias + 128 + ch);
    float bc = __ldg(bias + 192 + ch);

    float cst = 0.5f;
    float* h1 = g_h1raw + 64;

#pragma unroll 1
    for (int s = 0; s < S_; ++s) {
        int frame = b * S_ + s;
        const float* gg = g_gates + (size_t)frame * 256 * GST + p;
        float it = sigm(gg[(size_t)(ch)       * GST] + bi);
        float ft = sigm(gg[(size_t)(64 + ch)  * GST] + bf);
        float ot = sigm(gg[(size_t)(128 + ch) * GST] + bo);
        float cd =      gg[(size_t)(192 + ch) * GST] + bc;
        float gd = (cd >= 0.0f) ? (cd + 0.5f) : sigm(cd);
        float inv = 1.0f / (it + ft);
        cst = (ft * inv) * cst + (it * inv) * gd;
        float hv = ot * cst;
        if (PADOUT)
            h1[((size_t)frame * CL_ + ch) * PPLANE + p] = hv;
        else
            out[((size_t)frame * CL_ + ch) * HW_ + px] = hv;
    }
}

// ---------------- launch ----------------
extern "C" void kernel_launch(void* const* d_in, const int* in_sizes, int n_in,
                              void* d_out, int out_size)
{
    const float* x  = (const float*)d_in[0];
    const float* w0 = (const float*)d_in[1];
    const float* b0 = (const float*)d_in[2];
    const float* w1 = (const float*)d_in[3];
    const float* b1 = (const float*)d_in[4];
    float* out = (float*)d_out;

    k_zero<<<1024, 256>>>();
    k_fill_x<<<2048, 256>>>(x);
    k_pack_w<<<256, 256>>>(w0, w1);

    dim3 gg(NF * NT, 2, 1);   // 1152 x 2 CTAs
    k_gemm0<<<gg, 128>>>();
    k_scan<true><<<1024, 256>>>(b0, nullptr);
    k_gemm1<<<gg, 128>>>();
    k_scan<false><<<1024, 256>>>(b1, out);
}

// round 8
// speedup vs baseline: 3.0919x; 1.2758x over previous
#include <cuda_runtime.h>
#include <cuda_fp16.h>
#include <cstdint>

// ---------------- problem constants ----------------
#define B_     4
#define S_     16
#define NF     64            // frames = B*S
#define H_     32
#define W_     32
#define HW_    1024
#define CL_    64            // LSTM channels per layer; gate channels = 256
#define PR     34            // padded row width
#define PPLANE 1156          // 34*34
#define GST    1152          // gates scratch stride (18 N-tiles of 64)
#define NT     18            // N tiles per frame
#define KPA    72            // A smem row stride in halves (conflict-free ldsm)
#define KPB    40            // B smem row stride in halves

// ---------------- device scratch (static; no allocations) ----------------
__device__ float g_xraw [(size_t)NF * 32  * PPLANE + 64 + 2048];  // padded x (+guards)
__device__ float g_h1raw[(size_t)NF * CL_ * PPLANE + 64 + 2048];  // padded h0 (+guards)
__device__ float g_gates[(size_t)NF * 256 * GST];                 // conv outputs
// fp16 exact-split weights: [chunk][256 oc][64]  (k = [ah | al], a = ah+al exactly)
__device__ __align__(16) __half g_wp0[9  * 256 * 64];
__device__ __align__(16) __half g_wp1[18 * 256 * 64];

__constant__ int c_tapoff[9] = { -35, -34, -33, -1, 0, 1, 33, 34, 35 };

// ---------------- helpers ----------------
__device__ __forceinline__ float sigm(float x) { return 1.0f / (1.0f + __expf(-x)); }

__device__ __forceinline__ uint32_t smem_u32(const void* p) {
    uint32_t a;
    asm("{ .reg .u64 t; cvta.to.shared.u64 t, %1; cvt.u32.u64 %0, t; }" : "=r"(a) : "l"(p));
    return a;
}

__device__ __forceinline__ void ldsm4(uint32_t r[4], uint32_t addr) {
    asm volatile("ldmatrix.sync.aligned.m8n8.x4.shared.b16 {%0,%1,%2,%3}, [%4];"
        : "=r"(r[0]), "=r"(r[1]), "=r"(r[2]), "=r"(r[3]) : "r"(addr));
}

__device__ __forceinline__ void mma16816(float d[4], const uint32_t a[4],
                                         uint32_t b0, uint32_t b1) {
    asm volatile(
        "mma.sync.aligned.m16n8k16.row.col.f32.f16.f16.f32 "
        "{%0,%1,%2,%3}, {%4,%5,%6,%7}, {%8,%9}, {%0,%1,%2,%3};"
        : "+f"(d[0]), "+f"(d[1]), "+f"(d[2]), "+f"(d[3])
        : "r"(a[0]), "r"(a[1]), "r"(a[2]), "r"(a[3]), "r"(b0), "r"(b1));
}

__device__ __forceinline__ uint32_t hpack(float lo, float hi) {
    uint16_t l = __half_as_ushort(__float2half_rn(lo));
    uint16_t h = __half_as_ushort(__float2half_rn(hi));
    return (uint32_t)l | ((uint32_t)h << 16);
}

// ---------------- prologue kernels ----------------
__global__ void k_zero() {
    const size_t n1 = sizeof(g_xraw) / 4, n2 = sizeof(g_h1raw) / 4;
    for (size_t i = blockIdx.x * blockDim.x + threadIdx.x; i < n1 + n2;
         i += (size_t)gridDim.x * blockDim.x) {
        if (i < n1) g_xraw[i] = 0.0f; else g_h1raw[i - n1] = 0.0f;
    }
}

__global__ void k_fill_x(const float* __restrict__ x) {
    float* xp = g_xraw + 64;
    const int n = NF * 32 * HW_;
    for (int i = blockIdx.x * blockDim.x + threadIdx.x; i < n;
         i += gridDim.x * blockDim.x) {
        int plane = i >> 10, px = i & 1023;
        int r = px >> 5, c = px & 31;
        xp[(size_t)plane * PPLANE + (r + 1) * PR + (c + 1)] = x[i];
    }
}

// fp16 exact split packing: chunk ch covers tap=ch/CPT, ci0=(ch%CPT)*32.
// per oc row (64): [0..31]=ah, [32..63]=al with a = ah + al exactly.
__global__ void k_pack_w(const float* __restrict__ w0, const float* __restrict__ w1) {
    const int n0 = 9 * 256 * 32, n1 = 18 * 256 * 32;
    for (int i = blockIdx.x * blockDim.x + threadIdx.x; i < n0 + n1;
         i += gridDim.x * blockDim.x) {
        if (i < n0) {
            int ci = i & 31, t = i >> 5, oc = t & 255, ch = t >> 8;  // ch = tap
            float v = w0[((size_t)oc * 32 + ci) * 9 + ch];
            __half ah = __float2half_rn(v);
            __half al = __float2half_rn(v - __half2float(ah));
            __half* p = g_wp0 + ((size_t)ch * 256 + oc) * 64;
            p[ci] = ah; p[32 + ci] = al;
        } else {
            int j = i - n0;
            int ci = j & 31, t = j >> 5, oc = t & 255, ch = t >> 8;  // ch 0..17
            int tap = ch >> 1, ci0 = (ch & 1) * 32;
            float v = w1[((size_t)oc * 64 + ci0 + ci) * 9 + tap];
            __half ah = __float2half_rn(v);
            __half al = __float2half_rn(v - __half2float(ah));
            __half* p = g_wp1 + ((size_t)ch * 256 + oc) * 64;
            p[ci] = ah; p[32 + ci] = al;
        }
    }
}

// ---------------- GEMM kernel ----------------
// CTA = 128 threads (4 warps). Tile: M=128 gate channels x N=64 padded pixels,
// one frame. K loop: 9*CPT chunks; each chunk = 32 ci -> K_eff=64 ([ah|al] vs
// bh reused: ksteps 0,1 = ah*bh; ksteps 2,3 = al*bh at the same B columns).
template <int CPT>   // chunks per tap: 1 (CIN=32) or 2 (CIN=64)
__device__ __forceinline__ void gemm_body(const float* __restrict__ xpad,
                                          const __half* __restrict__ wp,
                                          float* __restrict__ gates)
{
    __shared__ __align__(16) __half sA[128 * KPA];   // 18.4 KB
    __shared__ __align__(16) __half sB[64 * KPB];    // 5.1 KB

    const int tid  = threadIdx.x, w = tid >> 5, lane = tid & 31;
    const int frame = blockIdx.x / NT, ntile = blockIdx.x - frame * NT;
    const int mtile = blockIdx.y;
    const int p0 = ntile * 64;
    const int NCH = 9 * CPT;

    const float* xf = xpad + (size_t)frame * (CPT * 32) * PPLANE;
    const uint32_t sAu = smem_u32(sA), sBu = smem_u32(sB);

    float d[2][8][4];
#pragma unroll
    for (int mt = 0; mt < 2; ++mt)
#pragma unroll
        for (int nt = 0; nt < 8; ++nt)
#pragma unroll
            for (int q = 0; q < 4; ++q) d[mt][nt][q] = 0.0f;

#pragma unroll 1
    for (int ch = 0; ch < NCH; ++ch) {
        const int tap = (CPT == 1) ? ch : (ch >> 1);
        const int ci0 = (CPT == 1) ? 0 : ((ch & 1) * 32);
        const int to  = c_tapoff[tap];

        __syncthreads();   // previous iter's ldsm reads done

        // ---- stage A: 128 rows x 64 halves ([ah|al]) ----
        {
            const __half* ag = wp + ((size_t)ch * 256 + mtile * 128) * 64;
            const int r8 = lane & 7, cg = lane >> 3;   // cg 0..3
#pragma unroll
            for (int ri = 0; ri < 4; ++ri) {
                int r = ri * 32 + w * 8 + r8;
#pragma unroll
                for (int cj = 0; cj < 2; ++cj) {
                    int c = cj * 4 + cg;               // 16B chunk 0..7
                    uint4 v = *(const uint4*)(ag + (size_t)r * 64 + c * 8);
                    *(uint4*)(sA + r * KPA + c * 8) = v;
                }
            }
        }
        // ---- stage B: 64 rows x 32 halves (bh only) from padded fp32 planes ----
        {
            const int r8 = lane & 7, cig = lane >> 3;  // ci group of 8
#pragma unroll
            for (int pi = 0; pi < 2; ++pi) {
                int row = pi * 32 + w * 8 + r8;        // 0..63 (pixel in tile)
                const float* xs = xf + (size_t)ci0 * PPLANE + p0 + row + to;
                float v[8];
#pragma unroll
                for (int j = 0; j < 8; ++j)
                    v[j] = __ldg(xs + (size_t)(cig * 8 + j) * PPLANE);
                uint4 hv;
                uint32_t* hw = (uint32_t*)&hv;
#pragma unroll
                for (int j = 0; j < 4; ++j)
                    hw[j] = hpack(v[2 * j], v[2 * j + 1]);
                *(uint4*)(sB + row * KPB + cig * 8) = hv;
            }
        }
        __syncthreads();

        // ---- mma: 4 k-steps of 16; B columns wrap (bh reused for al) ----
#pragma unroll
        for (int ks = 0; ks < 4; ++ks) {
            uint32_t a[2][4], b[4][4];
#pragma unroll
            for (int mt = 0; mt < 2; ++mt) {
                int rowA = w * 32 + mt * 16 + (lane & 15);
                int kcol = ks * 16 + (lane >> 4) * 8;
                ldsm4(a[mt], sAu + (uint32_t)(rowA * KPA + kcol) * 2);
            }
#pragma unroll
            for (int np = 0; np < 4; ++np) {
                int rowB = np * 16 + ((lane >> 4) & 1) * 8 + (lane & 7);
                int kcol = (ks & 1) * 16 + ((lane >> 3) & 1) * 8;
                ldsm4(b[np], sBu + (uint32_t)(rowB * KPB + kcol) * 2);
            }
#pragma unroll
            for (int mt = 0; mt < 2; ++mt)
#pragma unroll
                for (int nt = 0; nt < 8; ++nt)
                    mma16816(d[mt][nt], a[mt], b[nt >> 1][(nt & 1) * 2],
                             b[nt >> 1][(nt & 1) * 2 + 1]);
        }
    }

    // ---- epilogue: D -> gates scratch ----
    const int g4 = lane >> 2, t4 = lane & 3;
#pragma unroll
    for (int mt = 0; mt < 2; ++mt) {
        size_t rowbase = (size_t)frame * 256 + mtile * 128 + w * 32 + mt * 16 + g4;
#pragma unroll
        for (int nt = 0; nt < 8; ++nt) {
            float* gp = gates + rowbase * GST + p0 + nt * 8 + t4 * 2;
            *(float2*)gp                     = make_float2(d[mt][nt][0], d[mt][nt][1]);
            *(float2*)(gp + 8 * (size_t)GST) = make_float2(d[mt][nt][2], d[mt][nt][3]);
        }
    }
}

__global__ void __launch_bounds__(128)
k_gemm0() { gemm_body<1>(g_xraw + 64, g_wp0, g_gates); }

__global__ void __launch_bounds__(128)
k_gemm1() { gemm_body<2>(g_h1raw + 64, g_wp1, g_gates); }

// ---------------- scan kernels ----------------
// thread = (b, lstm-channel, interior pixel); loops s with cell state in a register.
template <bool PADOUT>
__global__ void __launch_bounds__(256)
k_scan(const float* __restrict__ bias, float* __restrict__ out)
{
    int gtid = blockIdx.x * blockDim.x + threadIdx.x;  // 0 .. 262143
    int px = gtid & 1023;
    int ch = (gtid >> 10) & 63;
    int b  = gtid >> 16;
    int r = px >> 5, c = px & 31;
    int p = (r + 1) * PR + (c + 1);

    float bi = __ldg(bias + ch);
    float bf = __ldg(bias + 64 + ch);
    float bo = __ldg(bias + 128 + ch);
    float bc = __ldg(bias + 192 + ch);

    float cst = 0.5f;
    float* h1 = g_h1raw + 64;

#pragma unroll 1
    for (int s = 0; s < S_; ++s) {
        int frame = b * S_ + s;
        const float* gg = g_gates + (size_t)frame * 256 * GST + p;
        float it = sigm(gg[(size_t)(ch)       * GST] + bi);
        float ft = sigm(gg[(size_t)(64 + ch)  * GST] + bf);
        float ot = sigm(gg[(size_t)(128 + ch) * GST] + bo);
        float cd =      gg[(size_t)(192 + ch) * GST] + bc;
        float gd = (cd >= 0.0f) ? (cd + 0.5f) : sigm(cd);
        float inv = 1.0f / (it + ft);
        cst = (ft * inv) * cst + (it * inv) * gd;
        float hv = ot * cst;
        if (PADOUT)
            h1[((size_t)frame * CL_ + ch) * PPLANE + p] = hv;
        else
            out[((size_t)frame * CL_ + ch) * HW_ + px] = hv;
    }
}

// ---------------- launch ----------------
extern "C" void kernel_launch(void* const* d_in, const int* in_sizes, int n_in,
                              void* d_out, int out_size)
{
    const float* x  = (const float*)d_in[0];
    const float* w0 = (const float*)d_in[1];
    const float* b0 = (const float*)d_in[2];
    const float* w1 = (const float*)d_in[3];
    const float* b1 = (const float*)d_in[4];
    float* out = (float*)d_out;

    k_zero<<<1024, 256>>>();
    k_fill_x<<<2048, 256>>>(x);
    k_pack_w<<<256, 256>>>(w0, w1);

    dim3 gg(NF * NT, 2, 1);   // 1152 x 2 CTAs
    k_gemm0<<<gg, 128>>>();
    k_scan<true><<<1024, 256>>>(b0, nullptr);
    k_gemm1<<<gg, 128>>>();
    k_scan<false><<<1024, 256>>>(b1, out);
}